// round 4
// baseline (speedup 1.0000x reference)
#include <cuda_runtime.h>

// The reference block is the identity on x (relu of the strictly negative
// AdderNet outputs is exactly 0; 0.1f*0 + x == x bitwise in fp32).
//
// R2 showed the user-kernel copy is overhead-bound (issue=1.8%, kernel
// 4.4us vs dur_us 5.28us). A/B: a single graph memcpy node via the driver's
// tuned D2D path (explicitly allowed by the harness rules).
// R3 run was lost to a container infra failure ("GB300 container failed
// twice") — resubmitting the identical experiment.

extern "C" void kernel_launch(void* const* d_in, const int* in_sizes, int n_in,
                              void* d_out, int out_size) {
    // out_size floats = 409600 * 4 bytes = 1.6384 MB device-to-device.
    cudaMemcpyAsync(d_out, d_in[0], (size_t)out_size * sizeof(float),
                    cudaMemcpyDeviceToDevice);
}